// round 14
// baseline (speedup 1.0000x reference)
#include <cuda_runtime.h>
#include <cuda_fp16.h>
#include <cstdint>

#define B_SZ   4
#define C_LEN  2048
#define H_N    8
#define DK_    64
#define DV_    128
#define DIN_   1024
#define QK_COLS 512
#define V_COLS  1024
#define M_ROWS  8192
#define NZ      32

typedef unsigned int u32;
typedef unsigned short u16;

// ----------------------- device scratch (no allocs) -----------------------
__device__ __align__(16) __half g_xs_h[M_ROWS * DIN_];
__device__ __align__(16) __half g_wq_h[QK_COLS * DIN_];
__device__ __align__(16) __half g_wk_h[QK_COLS * DIN_];
__device__ __align__(16) __half g_wv_h[V_COLS * DIN_];
__device__ __align__(16) __half g_wo_h[V_COLS * V_COLS];
__device__ __align__(16) __half g_q_h[M_ROWS * QK_COLS];
__device__ __align__(16) __half g_k_h[M_ROWS * QK_COLS];
__device__ __align__(16) __half g_e_h[(size_t)NZ * C_LEN * C_LEN];  // 256MB
__device__ __align__(16) __half g_v_h[M_ROWS * V_COLS];
__device__ __align__(16) __half g_vt_h[M_ROWS * V_COLS];
__device__ __align__(16) __half g_ao_h[M_ROWS * V_COLS];
__device__ __align__(16) float g_sum[NZ * C_LEN];

// ----------------------- helpers -----------------------
__device__ __forceinline__ u32 smem_u32(const void* p) {
    return (u32)__cvta_generic_to_shared(p);
}
__device__ __forceinline__ void ldsm4(u32* r, u32 a) {
    asm volatile("ldmatrix.sync.aligned.m8n8.x4.shared.b16 {%0,%1,%2,%3}, [%4];\n"
                 : "=r"(r[0]), "=r"(r[1]), "=r"(r[2]), "=r"(r[3]) : "r"(a));
}
__device__ __forceinline__ void mma16816(float* d, const u32* a, u32 b0, u32 b1) {
    asm volatile(
        "mma.sync.aligned.m16n8k16.row.col.f32.f16.f16.f32 "
        "{%0,%1,%2,%3},{%4,%5,%6,%7},{%8,%9},{%0,%1,%2,%3};\n"
        : "+f"(d[0]), "+f"(d[1]), "+f"(d[2]), "+f"(d[3])
        : "r"(a[0]), "r"(a[1]), "r"(a[2]), "r"(a[3]), "r"(b0), "r"(b1));
}
__device__ __forceinline__ void mma16816_h(u32* d, const u32* a, u32 b0, u32 b1) {
    asm volatile(
        "mma.sync.aligned.m16n8k16.row.col.f16.f16.f16.f16 "
        "{%0,%1},{%2,%3,%4,%5},{%6,%7},{%0,%1};\n"
        : "+r"(d[0]), "+r"(d[1])
        : "r"(a[0]), "r"(a[1]), "r"(a[2]), "r"(a[3]), "r"(b0), "r"(b1));
}
__device__ __forceinline__ u32 ex2_h2(u32 arg) {
    u32 r;
    asm("ex2.approx.f16x2 %0, %1;" : "=r"(r) : "r"(arg));
    return r;
}
#define CP16(dst, src) asm volatile("cp.async.cg.shared.global [%0], [%1], 16;\n" :: "r"(dst), "l"(src))
#define CPCOMMIT()     asm volatile("cp.async.commit_group;\n")
#define CPWAIT(n)      asm volatile("cp.async.wait_group %0;\n" :: "n"(n))

// ----------------------- merged fp32->fp16 split of all 5 inputs + zero g_sum -----------------------
#define SPL_N0 (M_ROWS * DIN_ / 4)
#define SPL_N1 (SPL_N0 + QK_COLS * DIN_ / 4)
#define SPL_N2 (SPL_N1 + QK_COLS * DIN_ / 4)
#define SPL_N3 (SPL_N2 + V_COLS * DIN_ / 4)
#define SPL_N4 (SPL_N3 + V_COLS * V_COLS / 4)
#define SPL_N5 (SPL_N4 + NZ * C_LEN / 4)
__global__ void __launch_bounds__(256) split_all(
    const float* __restrict__ x, const float* __restrict__ mq,
    const float* __restrict__ mk, const float* __restrict__ mv,
    const float* __restrict__ wo)
{
    int i = blockIdx.x * 256 + threadIdx.x;
    if (i >= SPL_N5) return;
    if (i >= SPL_N4) {
        int j = (i - SPL_N4) * 4;
        float4 z; z.x = 0.f; z.y = 0.f; z.z = 0.f; z.w = 0.f;
        *(float4*)&g_sum[j] = z;
        return;
    }
    const float* s; __half* d; int off;
    if (i < SPL_N0)      { s = x;  d = g_xs_h; off = i; }
    else if (i < SPL_N1) { s = mq; d = g_wq_h; off = i - SPL_N0; }
    else if (i < SPL_N2) { s = mk; d = g_wk_h; off = i - SPL_N1; }
    else if (i < SPL_N3) { s = mv; d = g_wv_h; off = i - SPL_N2; }
    else                 { s = wo; d = g_wo_h; off = i - SPL_N3; }
    float4 v = ((const float4*)s)[off];
    __half2 a; a.x = __float2half_rn(v.x); a.y = __float2half_rn(v.y);
    __half2 b; b.x = __float2half_rn(v.z); b.y = __float2half_rn(v.w);
    uint2 hh; hh.x = *(u32*)&a; hh.y = *(u32*)&b;
    ((uint2*)d)[off] = hh;
}

// ---------------------------------------------------------------------------
// fp16 NT GEMM: C = A@B^T. BM=128, BN=128, BK=64. 256 thr = 8 warps (4m x 2n).
// 2-stage cp.async double buffer; 64 HMMA/warp between syncs (4 k-steps).
// MODE 0: f32 acc, fp32 out = acc*cscale + bias.
// MODE 1: f32 acc, fp16 out = acc*cscale (+bias if non-null).
// MODE 2: f16 acc, E = exp((acc+mask[q])/8) -> fp16 out + colsums of stored E.
// MODE 3: f16 acc, fp16 out = acc + bias.
// ---------------------------------------------------------------------------
#define NSTAGE 2
#define ROWW 72                        // u16 per row: 64 data + 8 pad (144B)
#define STG (128 * ROWW)               // u16 per tile stage
#define TILEB (STG * 2)                // 18432 bytes per tile stage
#define SMEM_DYN (NSTAGE * TILEB * 2)  // 73728 bytes (A + B regions)
template <int MODE>
__global__ void __launch_bounds__(256, 2) gemm_h2(
    const __half* __restrict__ Ah, const __half* __restrict__ Bh,
    const float* __restrict__ bias, const float* __restrict__ mask, float cscale,
    float* __restrict__ Cf, __half* __restrict__ Ch,
    int K, int lda, int ldb, int ldc,
    size_t sA, size_t sB, size_t sC)
{
    extern __shared__ __align__(16) u16 dyns[];
    u16* sA0 = dyns;
    u16* sB0 = dyns + NSTAGE * STG;

    const int tid = threadIdx.x;
    const int lane = tid & 31, wid = tid >> 5;
    const int wm = wid & 3, wn = wid >> 2;
    const int bm = blockIdx.y * 128, bn = blockIdx.x * 128;
    const int z = blockIdx.z;

    Ah += sA * z; Bh += sB * z;
    if (Cf) Cf += sC * z;
    if (Ch) Ch += sC * z;

    // staging: 128 rows x 128B per tile = 1024 x 16B pieces; 4 per thread
    const int sr = tid >> 3, sc = (tid & 7) * 8;
    size_t aoffs[4], boffs[4];
    u32 dA[4], dB[4];
#pragma unroll
    for (int it = 0; it < 4; it++) {
        const int r = it * 32 + sr;
        aoffs[it] = (size_t)(bm + r) * lda + sc;
        boffs[it] = (size_t)(bn + r) * ldb + sc;
        dA[it] = smem_u32(&sA0[r * ROWW + sc]);
        dB[it] = smem_u32(&sB0[r * ROWW + sc]);
    }

    const int grp = lane >> 3, l8 = lane & 7;
    const int amr = ((grp & 1) << 3) + l8, amc = (grp >> 1) << 3;
    const int bmr = ((grp >> 1) << 3) + l8, bmc = (grp & 1) << 3;
    u32 aH_ad[2], bH_ad[4];
#pragma unroll
    for (int mi = 0; mi < 2; mi++)
        aH_ad[mi] = smem_u32(&sA0[(wm * 32 + mi * 16 + amr) * ROWW + amc]);
#pragma unroll
    for (int p = 0; p < 4; p++)
        bH_ad[p] = smem_u32(&sB0[(wn * 64 + p * 16 + bmr) * ROWW + bmc]);

    constexpr bool HACC = (MODE >= 2);
    float accf[2][8][4];
    u32   acch[2][8][2];
    if constexpr (HACC) {
#pragma unroll
        for (int a = 0; a < 2; a++)
#pragma unroll
            for (int b = 0; b < 8; b++) { acch[a][b][0] = 0u; acch[a][b][1] = 0u; }
    } else {
#pragma unroll
        for (int a = 0; a < 2; a++)
#pragma unroll
            for (int b = 0; b < 8; b++)
#pragma unroll
                for (int d = 0; d < 4; d++) accf[a][b][d] = 0.f;
    }

    const int NC = K >> 6;   // 64-wide chunks

    auto stage = [&](int buf, int c) {
        const u32 so = buf * TILEB;
        const size_t k0 = (size_t)c << 6;
#pragma unroll
        for (int it = 0; it < 4; it++) {
            CP16(dA[it] + so, Ah + aoffs[it] + k0);
            CP16(dB[it] + so, Bh + boffs[it] + k0);
        }
    };

    stage(0, 0); CPCOMMIT();

    for (int c = 0; c < NC; ++c) {
        const int buf = c & 1;
        CPWAIT(0);            // chunk c landed
        __syncthreads();      // visible to all; buf^1 consumed (iter c-1)
        if (c + 1 < NC) { stage(buf ^ 1, c + 1); CPCOMMIT(); }

        const u32 so = buf * TILEB;
#pragma unroll
        for (int s = 0; s < 4; s++) {
            const u32 ko = so + s * 32;   // +16 elems = +32 bytes
            u32 aH[2][4], bH[4][4];
            ldsm4(aH[0], aH_ad[0] + ko);
            ldsm4(aH[1], aH_ad[1] + ko);
#pragma unroll
            for (int p = 0; p < 4; p++)
                ldsm4(bH[p], bH_ad[p] + ko);
#pragma unroll
            for (int mi = 0; mi < 2; mi++)
#pragma unroll
                for (int ni = 0; ni < 8; ni++) {
                    const int p = ni >> 1, q = (ni & 1) * 2;
                    if constexpr (HACC)
                        mma16816_h(acch[mi][ni], aH[mi], bH[p][q], bH[p][q + 1]);
                    else
                        mma16816(accf[mi][ni], aH[mi], bH[p][q], bH[p][q + 1]);
                }
        }
    }

    // ----------------- epilogue -----------------
    const float K2E = 0.18033688011112042f;   // log2(e)/8
    const int lr = lane >> 2, lc2 = (lane & 3) * 2;
#pragma unroll
    for (int mi = 0; mi < 2; mi++) {
        const int m0 = bm + wm * 32 + mi * 16 + lr;
        __half2 mk0h, mk8h;
        if (MODE == 2) {
            const float* mrow = mask + (size_t)(z >> 3) * C_LEN;
            mk0h = __float2half2_rn(mrow[m0] * K2E);
            mk8h = __float2half2_rn(mrow[m0 + 8] * K2E);
        }
#pragma unroll
        for (int ni = 0; ni < 8; ni++) {
            const int n0 = bn + wn * 64 + ni * 8 + lc2;
            if (MODE == 0) {
                float c0 = accf[mi][ni][0], c1 = accf[mi][ni][1];
                float c2 = accf[mi][ni][2], c3 = accf[mi][ni][3];
                float b0 = bias[n0], b1 = bias[n0 + 1];
                float2 o0; o0.x = c0 * cscale + b0; o0.y = c1 * cscale + b1;
                float2 o1; o1.x = c2 * cscale + b0; o1.y = c3 * cscale + b1;
                *(float2*)(Cf + (size_t)m0 * ldc + n0) = o0;
                *(float2*)(Cf + (size_t)(m0 + 8) * ldc + n0) = o1;
            } else if (MODE == 1) {
                float c0 = accf[mi][ni][0], c1 = accf[mi][ni][1];
                float c2 = accf[mi][ni][2], c3 = accf[mi][ni][3];
                float b0 = 0.f, b1 = 0.f;
                if (bias) { b0 = bias[n0]; b1 = bias[n0 + 1]; }
                __half2 p0, p1;
                p0.x = __float2half_rn(c0 * cscale + b0);
                p0.y = __float2half_rn(c1 * cscale + b1);
                p1.x = __float2half_rn(c2 * cscale + b0);
                p1.y = __float2half_rn(c3 * cscale + b1);
                *(u32*)(Ch + (size_t)m0 * ldc + n0) = *(u32*)&p0;
                *(u32*)(Ch + (size_t)(m0 + 8) * ldc + n0) = *(u32*)&p1;
            } else if (MODE == 3) {
                __half2 b2 = __floats2half2_rn(bias[n0], bias[n0 + 1]);
                __half2 o0 = __hadd2(*(__half2*)&acch[mi][ni][0], b2);
                __half2 o1 = __hadd2(*(__half2*)&acch[mi][ni][1], b2);
                *(u32*)(Ch + (size_t)m0 * ldc + n0) = *(u32*)&o0;
                *(u32*)(Ch + (size_t)(m0 + 8) * ldc + n0) = *(u32*)&o1;
            } else { // MODE 2
                const __half2 k2e2 = __float2half2_rn(K2E);
                __half2 s0 = *(__half2*)&acch[mi][ni][0];
                __half2 s1 = *(__half2*)&acch[mi][ni][1];
                __half2 a0 = __hfma2(s0, k2e2, mk0h);
                __half2 a1 = __hfma2(s1, k2e2, mk8h);
                u32 e0 = ex2_h2(*(u32*)&a0);
                u32 e1 = ex2_h2(*(u32*)&a1);
                *(u32*)(Ch + (size_t)m0 * ldc + n0) = e0;
                *(u32*)(Ch + (size_t)(m0 + 8) * ldc + n0) = e1;
                __half2 sums = __hadd2(*(__half2*)&e0, *(__half2*)&e1);
                float c0 = __low2float(sums), c1 = __high2float(sums);
                c0 += __shfl_xor_sync(0xffffffffu, c0, 4);
                c0 += __shfl_xor_sync(0xffffffffu, c0, 8);
                c0 += __shfl_xor_sync(0xffffffffu, c0, 16);
                c1 += __shfl_xor_sync(0xffffffffu, c1, 4);
                c1 += __shfl_xor_sync(0xffffffffu, c1, 8);
                c1 += __shfl_xor_sync(0xffffffffu, c1, 16);
                if (lane < 4) {
                    atomicAdd(&g_sum[z * C_LEN + n0], c0);
                    atomicAdd(&g_sum[z * C_LEN + n0 + 1], c1);
                }
            }
        }
    }
}

// ------- V'' transpose+scale: vt[z][d][k] = V[z][k][d] * 2048 / sum[z][k] -------
__global__ void __launch_bounds__(256) scale_v()
{
    __shared__ float t[32][33];
    const int z = blockIdx.z;
    const int k0 = blockIdx.x * 32, d0 = blockIdx.y * 32;
    const int tx = threadIdx.x & 31, ty = threadIdx.x >> 5;
    const size_t vbase = (size_t)z * (C_LEN * DV_);
#pragma unroll
    for (int i = 0; i < 4; i++)
        t[ty + i * 8][tx] = __half2float(
            g_v_h[vbase + (size_t)(k0 + ty + i * 8) * DV_ + d0 + tx]);
    __syncthreads();
    const float iv = 2048.0f / g_sum[z * C_LEN + k0 + tx];
#pragma unroll
    for (int i = 0; i < 4; i++) {
        float val = t[tx][ty + i * 8] * iv;
        size_t o = vbase + (size_t)(d0 + ty + i * 8) * C_LEN + k0 + tx;
        g_vt_h[o] = __float2half_rn(val);
    }
}

// ---------------------------------------------------------------------------
extern "C" void kernel_launch(void* const* d_in, const int* in_sizes, int n_in,
                              void* d_out, int out_size)
{
    const float* x    = (const float*)d_in[0];
    const float* mask = (const float*)d_in[1];
    const float* Mq_w = (const float*)d_in[2];
    const float* Mq_b = (const float*)d_in[3];
    const float* Mk_w = (const float*)d_in[4];
    const float* Mk_b = (const float*)d_in[5];
    const float* Mv_w = (const float*)d_in[6];
    const float* Mv_b = (const float*)d_in[7];
    const float* Wo_w = (const float*)d_in[8];
    const float* Wo_b = (const float*)d_in[9];
    float* out = (float*)d_out;

    __half *xs_h, *wq_h, *wk_h, *wv_h, *wo_h;
    __half *q_h, *k_h, *e_h, *v_h, *vt_h, *ao_h;
    cudaGetSymbolAddress((void**)&xs_h, g_xs_h);
    cudaGetSymbolAddress((void**)&wq_h, g_wq_h);
    cudaGetSymbolAddress((void**)&wk_h, g_wk_h);
    cudaGetSymbolAddress((void**)&wv_h, g_wv_h);
    cudaGetSymbolAddress((void**)&wo_h, g_wo_h);
    cudaGetSymbolAddress((void**)&q_h,  g_q_h);
    cudaGetSymbolAddress((void**)&k_h,  g_k_h);
    cudaGetSymbolAddress((void**)&e_h,  g_e_h);
    cudaGetSymbolAddress((void**)&v_h,  g_v_h);
    cudaGetSymbolAddress((void**)&vt_h, g_vt_h);
    cudaGetSymbolAddress((void**)&ao_h, g_ao_h);

    cudaFuncSetAttribute(gemm_h2<0>, cudaFuncAttributeMaxDynamicSharedMemorySize, SMEM_DYN);
    cudaFuncSetAttribute(gemm_h2<1>, cudaFuncAttributeMaxDynamicSharedMemorySize, SMEM_DYN);
    cudaFuncSetAttribute(gemm_h2<2>, cudaFuncAttributeMaxDynamicSharedMemorySize, SMEM_DYN);
    cudaFuncSetAttribute(gemm_h2<3>, cudaFuncAttributeMaxDynamicSharedMemorySize, SMEM_DYN);

    dim3 blk(256);

    split_all<<<(SPL_N5 + 255) / 256, blk>>>(x, Mq_w, Mk_w, Mv_w, Wo_w);

    // Q, K projections -> fp16 (f16 accumulators)
    gemm_h2<3><<<dim3(QK_COLS / 128, M_ROWS / 128, 1), blk, SMEM_DYN>>>(
        xs_h, wq_h, Mq_b, nullptr, 1.0f, nullptr, q_h,
        DIN_, DIN_, DIN_, QK_COLS, 0, 0, 0);
    gemm_h2<3><<<dim3(QK_COLS / 128, M_ROWS / 128, 1), blk, SMEM_DYN>>>(
        xs_h, wk_h, Mk_b, nullptr, 1.0f, nullptr, k_h,
        DIN_, DIN_, DIN_, QK_COLS, 0, 0, 0);
    // V projection -> fp16 (f32 acc)
    gemm_h2<1><<<dim3(V_COLS / 128, M_ROWS / 128, 1), blk, SMEM_DYN>>>(
        xs_h, wv_h, Mv_b, nullptr, 1.0f, nullptr, v_h,
        DIN_, DIN_, DIN_, V_COLS, 0, 0, 0);

    // scores -> E = exp((QK^T+mask)/8) fp16 + column sums (f16 acc)
    gemm_h2<2><<<dim3(C_LEN / 128, C_LEN / 128, NZ), blk, SMEM_DYN>>>(
        q_h, k_h, nullptr, mask, 1.0f, nullptr, e_h,
        DK_, DK_, DK_, C_LEN,
        (size_t)C_LEN * DK_, (size_t)C_LEN * DK_, (size_t)C_LEN * C_LEN);

    // V'' = V*2048/sum, transposed to [z][d][k]
    scale_v<<<dim3(C_LEN / 32, DV_ / 32, NZ), blk>>>();

    // AO = (E @ V''^T) / 2048  (f32 acc)
    gemm_h2<1><<<dim3(DV_ / 128, C_LEN / 128, NZ), blk, SMEM_DYN>>>(
        e_h, vt_h, nullptr, nullptr, 1.0f / 2048.0f, nullptr, ao_h,
        C_LEN, C_LEN, C_LEN, DV_,
        (size_t)C_LEN * C_LEN, (size_t)C_LEN * DV_, (size_t)C_LEN * DV_);

    // out projection -> d_out fp32 (f32 acc)
    gemm_h2<0><<<dim3(V_COLS / 128, M_ROWS / 128, 1), blk, SMEM_DYN>>>(
        ao_h, wo_h, Wo_b, nullptr, 1.0f, out, nullptr,
        V_COLS, V_COLS, V_COLS, V_COLS, 0, 0, 0);
}